// round 9
// baseline (speedup 1.0000x reference)
#include <cuda_runtime.h>
#include <cuda_fp16.h>
#include <cstdint>

// Problem constants (fixed by the dataset)
#define NNODES 50000
#define LEV 2
#define RR 2
#define BLK (RR*LEV)          // 4 framelet blocks
#define NNZ 800000
#define F_IN 128
#define F_OUT 64
#define ACT_B (BLK - (LEV-1)) // 3 active blocks (block 0's y is never used)
#define ROWS_T (ACT_B * NNODES)   // 150000 (b, r) rows
#define EDGES_T (ACT_B * NNZ)     // 2400000 active edges
#define NB1 ((ROWS_T + 255) / 256)  // 586 level-1 scan blocks
#define GEMM_THREADS 800000         // 3125 blocks * 256
#define PADDED_E (EDGES_T + 3 * ROWS_T)   // 2,850,000 (pad-4 worst case)

// ---------------------------------------------------------------------------
// Device-global scratch. h, y stored fp16 (half2-packed): one feature row =
// 64 halves = 128 B = 8 uint4. Edge list is SoA with row segments padded to
// multiples of 4 so int4/float4 batch loads are 16B-aligned.
//
// Cross-replay invariant: g_hist == 0 at entry. First (correctness) run gets
// this from BSS zero-init; spmm2_csr restores it after its final read, so
// every CUDA-graph replay starts from identical state.
// ---------------------------------------------------------------------------
__device__ uint4  g_h[(size_t)NNODES * 8];     // 6.4 MB
__device__ uint4  g_y[(size_t)ROWS_T * 8];     // 19.2 MB
__device__ int    g_hist[ROWS_T];              // per-(b,r) nnz
__device__ int    g_start[ROWS_T];             // block-local padded excl prefix
__device__ int    g_cursor[ROWS_T];            // scatter cursors (block-local)
__device__ int    g_part[1024];                // scan block partials
__device__ int4   g_ec4[(PADDED_E + 3) / 4];   // cols  (SoA) 11.4 MB
__device__ float4 g_ev4[(PADDED_E + 3) / 4];   // vals  (SoA) 11.4 MB
#define g_ec  ((int*)g_ec4)
#define g_evv ((float*)g_ev4)

__device__ __forceinline__ unsigned pack_h2(float a, float b) {
    __half2 h = __floats2half2_rn(a, b);
    return *reinterpret_cast<unsigned*>(&h);
}
__device__ __forceinline__ float2 unpack_h2(unsigned u) {
    __half2 h = *reinterpret_cast<__half2*>(&u);
    return __half22float2(h);
}
__device__ __forceinline__ void accum8(float* acc, float v, uint4 hv) {
    const float2 f0 = unpack_h2(hv.x);
    const float2 f1 = unpack_h2(hv.y);
    const float2 f2 = unpack_h2(hv.z);
    const float2 f3 = unpack_h2(hv.w);
    acc[0] += v * f0.x; acc[1] += v * f0.y;
    acc[2] += v * f1.x; acc[3] += v * f1.y;
    acc[4] += v * f2.x; acc[5] += v * f2.y;
    acc[6] += v * f3.x; acc[7] += v * f3.y;
}

// ---------------------------------------------------------------------------
// Kernel 1: h = x @ W (fp32 compute, fp16 store) + fused edge histogram.
// ---------------------------------------------------------------------------
__global__ __launch_bounds__(256) void gemm_xw(const float* __restrict__ x,
                                               const float* __restrict__ w,
                                               const int*   __restrict__ rows) {
    const int t  = threadIdx.x;
    const int gt = blockIdx.x * 256 + t;

    __shared__ float4 ws[F_IN * (F_OUT/4)];   // 32 KB
    __shared__ float4 xs[16 * (F_IN/4)];      // 8 KB

    // Histogram: 3 strided edges per thread (3 * 800000 == EDGES_T).
    // Fire-and-forget REDs whose latency hides under the GEMM below.
    #pragma unroll
    for (int s = 0; s < 3; s++) {
        const int e = gt + s * GEMM_THREADS;
        const int b = e / NNZ;
        const int i = e - b * NNZ;
        const int r = rows[(size_t)(b + 1) * NNZ + i];
        atomicAdd(&g_hist[b * NNODES + r], 1);
    }

    #pragma unroll
    for (int i = 0; i < 8; i++)
        ws[t + i * 256] = ((const float4*)w)[t + i * 256];

    const size_t row0 = (size_t)blockIdx.x * 16;
    #pragma unroll
    for (int i = 0; i < 2; i++)
        xs[t + i * 256] = ((const float4*)x)[row0 * (F_IN/4) + t + i * 256];

    __syncthreads();

    const int fi = t & 15;
    const int ri = t >> 4;
    float4 acc = make_float4(0.f, 0.f, 0.f, 0.f);

    #pragma unroll
    for (int k = 0; k < F_IN; k += 4) {
        const float4 xv = xs[ri * (F_IN/4) + (k >> 2)];
        const float4 w0 = ws[(k + 0) * 16 + fi];
        const float4 w1 = ws[(k + 1) * 16 + fi];
        const float4 w2 = ws[(k + 2) * 16 + fi];
        const float4 w3 = ws[(k + 3) * 16 + fi];
        acc.x += xv.x * w0.x + xv.y * w1.x + xv.z * w2.x + xv.w * w3.x;
        acc.y += xv.x * w0.y + xv.y * w1.y + xv.z * w2.y + xv.w * w3.y;
        acc.z += xv.x * w0.z + xv.y * w1.z + xv.z * w2.z + xv.w * w3.z;
        acc.w += xv.x * w0.w + xv.y * w1.w + xv.z * w2.w + xv.w * w3.w;
    }
    uint2 p;
    p.x = pack_h2(acc.x, acc.y);
    p.y = pack_h2(acc.z, acc.w);
    ((uint2*)g_h)[(row0 + ri) * 16 + fi] = p;
}

// ---------------------------------------------------------------------------
// scan1: block-local exclusive prefix of PADDED lengths ((len+3)&~3) via
// warp shuffles. Seeds cursors; writes padded block totals to g_part.
// ---------------------------------------------------------------------------
__global__ __launch_bounds__(256) void scan1() {
    __shared__ int wsum[8];
    const int t = threadIdx.x;
    const int lane = t & 31;
    const int wid = t >> 5;
    const int idx = blockIdx.x * 256 + t;
    const int v  = (idx < ROWS_T) ? g_hist[idx] : 0;
    const int pv = (v + 3) & ~3;

    int x = pv;                               // inclusive warp scan
    #pragma unroll
    for (int off = 1; off < 32; off <<= 1) {
        const int n = __shfl_up_sync(0xffffffffu, x, off);
        if (lane >= off) x += n;
    }
    if (lane == 31) wsum[wid] = x;
    __syncthreads();
    if (t < 8) {
        const int orig = wsum[t];
        int s = orig;
        #pragma unroll
        for (int off = 1; off < 8; off <<= 1) {
            const int n = __shfl_up_sync(0x000000ffu, s, off);
            if (t >= off) s += n;
        }
        wsum[t] = s - orig;                   // exclusive warp offsets
    }
    __syncthreads();
    const int ex = x - pv + wsum[wid];        // block-local exclusive (padded)
    if (idx < ROWS_T) {
        g_start[idx]  = ex;
        g_cursor[idx] = ex;
    }
    if (t == 255) g_part[blockIdx.x] = ex + pv;   // padded block total
}

// ---------------------------------------------------------------------------
// scan2: 640 threads (20 warps) exclusive-scan the 586 block totals.
// ---------------------------------------------------------------------------
__global__ __launch_bounds__(640) void scan2() {
    __shared__ int wsum[20];
    const int t = threadIdx.x;
    const int lane = t & 31;
    const int wid = t >> 5;
    const int v = (t < NB1) ? g_part[t] : 0;

    int x = v;
    #pragma unroll
    for (int off = 1; off < 32; off <<= 1) {
        const int n = __shfl_up_sync(0xffffffffu, x, off);
        if (lane >= off) x += n;
    }
    if (lane == 31) wsum[wid] = x;
    __syncthreads();
    if (t < 32) {
        const int orig = (t < 20) ? wsum[t] : 0;
        int s = orig;
        #pragma unroll
        for (int off = 1; off < 32; off <<= 1) {
            const int n = __shfl_up_sync(0xffffffffu, s, off);
            if (t >= off) s += n;
        }
        if (t < 20) wsum[t] = s - orig;
    }
    __syncthreads();
    if (t < NB1) g_part[t] = x - v + wsum[wid];   // exclusive global offset
}

// ---------------------------------------------------------------------------
// Scatter: 2 edges per thread into SoA (cols, vals), row-sorted, padded segs.
// ---------------------------------------------------------------------------
__global__ __launch_bounds__(256) void scatter(const float* __restrict__ vals,
                                               const int*   __restrict__ rows,
                                               const int*   __restrict__ cols) {
    const int p = blockIdx.x * 256 + threadIdx.x;
    if (p >= EDGES_T / 2) return;
    const int2   rp = ((const int2*)(rows + NNZ))[p];
    const int2   cp = ((const int2*)(cols + NNZ))[p];
    const float2 vp = ((const float2*)(vals + NNZ))[p];
    const int base = ((2 * p) / NNZ) * NNODES;

    const int bk0 = base + rp.x;
    const int pos0 = atomicAdd(&g_cursor[bk0], 1) + g_part[bk0 >> 8];
    g_ec[pos0]  = cp.x;
    g_evv[pos0] = vp.x;

    const int bk1 = base + rp.y;
    const int pos1 = atomicAdd(&g_cursor[bk1], 1) + g_part[bk1 >> 8];
    g_ec[pos1]  = cp.y;
    g_evv[pos1] = vp.y;
}

// ---------------------------------------------------------------------------
// SpMM-1 (CSR gather, 4-edge batched): y[b][r] = filt * sum v_e * h[c_e]
// 8 lanes per row; lane owns one uint4 (8 halves). beg is 16B-aligned (pad-4).
// ---------------------------------------------------------------------------
__global__ __launch_bounds__(256) void spmm1_csr(const float* __restrict__ filt) {
    const int gid = blockIdx.x * 256 + threadIdx.x;
    const int row = gid >> 3;
    if (row >= ROWS_T) return;
    const int q = gid & 7;
    const int beg = g_start[row] + g_part[row >> 8];
    const int len = g_hist[row];
    const int b = row / NNODES;
    const int r = row - b * NNODES;

    float acc[8];
    #pragma unroll
    for (int k = 0; k < 8; k++) acc[k] = 0.f;

    const int*   ec = g_ec  + beg;
    const float* ev = g_evv + beg;
    int j = 0;
    for (; j + 4 <= len; j += 4) {
        const int4   c4 = *(const int4*)(ec + j);
        const float4 v4 = *(const float4*)(ev + j);
        const uint4 ha = g_h[(size_t)c4.x * 8 + q];
        const uint4 hb = g_h[(size_t)c4.y * 8 + q];
        const uint4 hc = g_h[(size_t)c4.z * 8 + q];
        const uint4 hd = g_h[(size_t)c4.w * 8 + q];
        accum8(acc, v4.x, ha);
        accum8(acc, v4.y, hb);
        accum8(acc, v4.z, hc);
        accum8(acc, v4.w, hd);
    }
    for (; j < len; j++) {
        const uint4 h = g_h[(size_t)ec[j] * 8 + q];
        accum8(acc, ev[j], h);
    }

    const float f = filt[(size_t)(b + 1) * NNODES + r];
    uint4 o;
    o.x = pack_h2(f * acc[0], f * acc[1]);
    o.y = pack_h2(f * acc[2], f * acc[3]);
    o.z = pack_h2(f * acc[4], f * acc[5]);
    o.w = pack_h2(f * acc[6], f * acc[7]);
    g_y[(size_t)row * 8 + q] = o;
}

// ---------------------------------------------------------------------------
// SpMM-2 (CSR gather, 4-edge batched): out[r] = bias + sum_b sum v_e * y[b][c]
// Restores g_hist = 0 after its final read (warp-local slot: the warp-wide
// LDG precedes lane-0's STG in program order; no other warp reads the slot).
// ---------------------------------------------------------------------------
__global__ __launch_bounds__(256) void spmm2_csr(float* __restrict__ out,
                                                 const float* __restrict__ bias) {
    const int gid = blockIdx.x * 256 + threadIdx.x;
    const int r = gid >> 3;
    if (r >= NNODES) return;
    const int q = gid & 7;

    float acc[8];
    #pragma unroll
    for (int k = 0; k < 8; k++) acc[k] = bias[q * 8 + k];

    #pragma unroll
    for (int b = 0; b < ACT_B; b++) {
        const int row = b * NNODES + r;
        const int beg = g_start[row] + g_part[row >> 8];
        const int len = g_hist[row];
        if (q == 0) g_hist[row] = 0;
        const size_t ybase = (size_t)b * NNODES * 8;
        const int*   ec = g_ec  + beg;
        const float* ev = g_evv + beg;
        int j = 0;
        for (; j + 4 <= len; j += 4) {
            const int4   c4 = *(const int4*)(ec + j);
            const float4 v4 = *(const float4*)(ev + j);
            const uint4 ya = g_y[ybase + (size_t)c4.x * 8 + q];
            const uint4 yb = g_y[ybase + (size_t)c4.y * 8 + q];
            const uint4 yc = g_y[ybase + (size_t)c4.z * 8 + q];
            const uint4 yd = g_y[ybase + (size_t)c4.w * 8 + q];
            accum8(acc, v4.x, ya);
            accum8(acc, v4.y, yb);
            accum8(acc, v4.z, yc);
            accum8(acc, v4.w, yd);
        }
        for (; j < len; j++) {
            const uint4 yv = g_y[ybase + (size_t)ec[j] * 8 + q];
            accum8(acc, ev[j], yv);
        }
    }
    float4* op = (float4*)(out + (size_t)r * F_OUT + q * 8);
    op[0] = make_float4(acc[0], acc[1], acc[2], acc[3]);
    op[1] = make_float4(acc[4], acc[5], acc[6], acc[7]);
}

// ---------------------------------------------------------------------------
// Launch: gemm(+hist), scan1, scan2, scatter, spmm1, spmm2(+hist restore)
// ---------------------------------------------------------------------------
extern "C" void kernel_launch(void* const* d_in, const int* in_sizes, int n_in,
                              void* d_out, int out_size) {
    const float* x    = (const float*)d_in[0];
    const float* wgt  = (const float*)d_in[1];
    const float* filt = (const float*)d_in[2];
    const float* bias = (const float*)d_in[3];
    const float* vals = (const float*)d_in[4];
    const int*   rows = (const int*)d_in[5];
    const int*   cols = (const int*)d_in[6];
    float* out = (float*)d_out;

    gemm_xw<<<NNODES / 16, 256>>>(x, wgt, rows);                   // #1
    scan1<<<NB1, 256>>>();                                         // #2
    scan2<<<1, 640>>>();                                           // #3
    scatter<<<(EDGES_T / 2 + 255) / 256, 256>>>(vals, rows, cols); // #4
    spmm1_csr<<<(ROWS_T * 8 + 255) / 256, 256>>>(filt);            // #5
    spmm2_csr<<<(NNODES * 8 + 255) / 256, 256>>>(out, bias);       // #6
}

// round 10
// speedup vs baseline: 1.1461x; 1.1461x over previous
#include <cuda_runtime.h>
#include <cuda_fp16.h>
#include <cstdint>

// Problem constants (fixed by the dataset)
#define NNODES 50000
#define LEV 2
#define RR 2
#define BLK (RR*LEV)          // 4 framelet blocks
#define NNZ 800000
#define F_IN 128
#define F_OUT 64
#define ACT_B (BLK - (LEV-1)) // 3 active blocks (block 0's y is never used)
#define ROWS_T (ACT_B * NNODES)   // 150000 (b, r) rows
#define EDGES_T (ACT_B * NNZ)     // 2400000 active edges
#define NB1 ((ROWS_T + 255) / 256)  // 586 level-1 scan blocks
#define GEMM_THREADS 800000         // 3125 blocks * 256
#define PADDED_E (EDGES_T + 3 * ROWS_T)   // 2,850,000 (pad-4 worst case)

// ---------------------------------------------------------------------------
// Device-global scratch. h, y stored fp16 (half2-packed): one feature row =
// 64 halves = 128 B = 8 uint4. Edge list is PACKED AoS: one edge = 4 bytes
// (uint16 col | fp16 val)<<16, row segments padded to %4 so one uint4 load
// fetches 4 edges, 16B-aligned.
//
// Cross-replay invariant: g_hist == 0 at entry (BSS zero-init for run 1;
// spmm2_csr restores it after its final read on every replay).
// ---------------------------------------------------------------------------
__device__ uint4  g_h[(size_t)NNODES * 8];     // 6.4 MB
__device__ uint4  g_y[(size_t)ROWS_T * 8];     // 19.2 MB
__device__ int    g_hist[ROWS_T];              // per-(b,r) nnz
__device__ int    g_start[ROWS_T];             // block-local padded excl prefix
__device__ int    g_cursor[ROWS_T];            // scatter cursors (block-local)
__device__ int    g_part[1024];                // scan block partials
__device__ uint4  g_ep4[(PADDED_E + 3) / 4];   // packed edges, 11.4 MB
#define g_ep ((unsigned*)g_ep4)

__device__ __forceinline__ unsigned pack_h2(float a, float b) {
    __half2 h = __floats2half2_rn(a, b);
    return *reinterpret_cast<unsigned*>(&h);
}
__device__ __forceinline__ float2 unpack_h2(unsigned u) {
    __half2 h = *reinterpret_cast<__half2*>(&u);
    return __half22float2(h);
}
__device__ __forceinline__ unsigned pack_edge(int c, float v) {
    return (unsigned)c | ((unsigned)__half_as_ushort(__float2half_rn(v)) << 16);
}
__device__ __forceinline__ float edge_val(unsigned e) {
    return __half2float(__ushort_as_half((unsigned short)(e >> 16)));
}
__device__ __forceinline__ void accum8(float* acc, float v, uint4 hv) {
    const float2 f0 = unpack_h2(hv.x);
    const float2 f1 = unpack_h2(hv.y);
    const float2 f2 = unpack_h2(hv.z);
    const float2 f3 = unpack_h2(hv.w);
    acc[0] += v * f0.x; acc[1] += v * f0.y;
    acc[2] += v * f1.x; acc[3] += v * f1.y;
    acc[4] += v * f2.x; acc[5] += v * f2.y;
    acc[6] += v * f3.x; acc[7] += v * f3.y;
}

// ---------------------------------------------------------------------------
// Kernel 1: h = x @ W (fp32 compute, fp16 store) + fused edge histogram.
// ---------------------------------------------------------------------------
__global__ __launch_bounds__(256) void gemm_xw(const float* __restrict__ x,
                                               const float* __restrict__ w,
                                               const int*   __restrict__ rows) {
    const int t  = threadIdx.x;
    const int gt = blockIdx.x * 256 + t;

    __shared__ float4 ws[F_IN * (F_OUT/4)];   // 32 KB
    __shared__ float4 xs[16 * (F_IN/4)];      // 8 KB

    // Histogram: 3 strided edges per thread (3 * 800000 == EDGES_T).
    #pragma unroll
    for (int s = 0; s < 3; s++) {
        const int e = gt + s * GEMM_THREADS;
        const int b = e / NNZ;
        const int i = e - b * NNZ;
        const int r = rows[(size_t)(b + 1) * NNZ + i];
        atomicAdd(&g_hist[b * NNODES + r], 1);
    }

    #pragma unroll
    for (int i = 0; i < 8; i++)
        ws[t + i * 256] = ((const float4*)w)[t + i * 256];

    const size_t row0 = (size_t)blockIdx.x * 16;
    #pragma unroll
    for (int i = 0; i < 2; i++)
        xs[t + i * 256] = ((const float4*)x)[row0 * (F_IN/4) + t + i * 256];

    __syncthreads();

    const int fi = t & 15;
    const int ri = t >> 4;
    float4 acc = make_float4(0.f, 0.f, 0.f, 0.f);

    #pragma unroll
    for (int k = 0; k < F_IN; k += 4) {
        const float4 xv = xs[ri * (F_IN/4) + (k >> 2)];
        const float4 w0 = ws[(k + 0) * 16 + fi];
        const float4 w1 = ws[(k + 1) * 16 + fi];
        const float4 w2 = ws[(k + 2) * 16 + fi];
        const float4 w3 = ws[(k + 3) * 16 + fi];
        acc.x += xv.x * w0.x + xv.y * w1.x + xv.z * w2.x + xv.w * w3.x;
        acc.y += xv.x * w0.y + xv.y * w1.y + xv.z * w2.y + xv.w * w3.y;
        acc.z += xv.x * w0.z + xv.y * w1.z + xv.z * w2.z + xv.w * w3.z;
        acc.w += xv.x * w0.w + xv.y * w1.w + xv.z * w2.w + xv.w * w3.w;
    }
    uint2 p;
    p.x = pack_h2(acc.x, acc.y);
    p.y = pack_h2(acc.z, acc.w);
    ((uint2*)g_h)[(row0 + ri) * 16 + fi] = p;
}

// ---------------------------------------------------------------------------
// scan1: block-local exclusive prefix of PADDED lengths ((len+3)&~3) via
// warp shuffles. Seeds cursors; writes padded block totals to g_part.
// ---------------------------------------------------------------------------
__global__ __launch_bounds__(256) void scan1() {
    __shared__ int wsum[8];
    const int t = threadIdx.x;
    const int lane = t & 31;
    const int wid = t >> 5;
    const int idx = blockIdx.x * 256 + t;
    const int v  = (idx < ROWS_T) ? g_hist[idx] : 0;
    const int pv = (v + 3) & ~3;

    int x = pv;                               // inclusive warp scan
    #pragma unroll
    for (int off = 1; off < 32; off <<= 1) {
        const int n = __shfl_up_sync(0xffffffffu, x, off);
        if (lane >= off) x += n;
    }
    if (lane == 31) wsum[wid] = x;
    __syncthreads();
    if (t < 8) {
        const int orig = wsum[t];
        int s = orig;
        #pragma unroll
        for (int off = 1; off < 8; off <<= 1) {
            const int n = __shfl_up_sync(0x000000ffu, s, off);
            if (t >= off) s += n;
        }
        wsum[t] = s - orig;                   // exclusive warp offsets
    }
    __syncthreads();
    const int ex = x - pv + wsum[wid];        // block-local exclusive (padded)
    if (idx < ROWS_T) {
        g_start[idx]  = ex;
        g_cursor[idx] = ex;
    }
    if (t == 255) g_part[blockIdx.x] = ex + pv;   // padded block total
}

// ---------------------------------------------------------------------------
// scan2: 640 threads (20 warps) exclusive-scan the 586 block totals.
// ---------------------------------------------------------------------------
__global__ __launch_bounds__(640) void scan2() {
    __shared__ int wsum[20];
    const int t = threadIdx.x;
    const int lane = t & 31;
    const int wid = t >> 5;
    const int v = (t < NB1) ? g_part[t] : 0;

    int x = v;
    #pragma unroll
    for (int off = 1; off < 32; off <<= 1) {
        const int n = __shfl_up_sync(0xffffffffu, x, off);
        if (lane >= off) x += n;
    }
    if (lane == 31) wsum[wid] = x;
    __syncthreads();
    if (t < 32) {
        const int orig = (t < 20) ? wsum[t] : 0;
        int s = orig;
        #pragma unroll
        for (int off = 1; off < 32; off <<= 1) {
            const int n = __shfl_up_sync(0xffffffffu, s, off);
            if (t >= off) s += n;
        }
        if (t < 20) wsum[t] = s - orig;
    }
    __syncthreads();
    if (t < NB1) g_part[t] = x - v + wsum[wid];   // exclusive global offset
}

// ---------------------------------------------------------------------------
// Scatter: 2 edges per thread; ONE 4-byte packed store per edge.
// ---------------------------------------------------------------------------
__global__ __launch_bounds__(256) void scatter(const float* __restrict__ vals,
                                               const int*   __restrict__ rows,
                                               const int*   __restrict__ cols) {
    const int p = blockIdx.x * 256 + threadIdx.x;
    if (p >= EDGES_T / 2) return;
    const int2   rp = ((const int2*)(rows + NNZ))[p];
    const int2   cp = ((const int2*)(cols + NNZ))[p];
    const float2 vp = ((const float2*)(vals + NNZ))[p];
    const int base = ((2 * p) / NNZ) * NNODES;

    const int bk0 = base + rp.x;
    const int pos0 = atomicAdd(&g_cursor[bk0], 1) + g_part[bk0 >> 8];
    g_ep[pos0] = pack_edge(cp.x, vp.x);

    const int bk1 = base + rp.y;
    const int pos1 = atomicAdd(&g_cursor[bk1], 1) + g_part[bk1 >> 8];
    g_ep[pos1] = pack_edge(cp.y, vp.y);
}

// ---------------------------------------------------------------------------
// SpMM-1 (CSR gather, 4-edge batched): y[b][r] = filt * sum v_e * h[c_e]
// 8 lanes per row; lane owns one uint4 (8 halves). One uint4 edge load = 4
// edges (beg is 16B-aligned via pad-4).
// ---------------------------------------------------------------------------
__global__ __launch_bounds__(256) void spmm1_csr(const float* __restrict__ filt) {
    const int gid = blockIdx.x * 256 + threadIdx.x;
    const int row = gid >> 3;
    if (row >= ROWS_T) return;
    const int q = gid & 7;
    const int beg = g_start[row] + g_part[row >> 8];
    const int len = g_hist[row];
    const int b = row / NNODES;
    const int r = row - b * NNODES;

    float acc[8];
    #pragma unroll
    for (int k = 0; k < 8; k++) acc[k] = 0.f;

    const unsigned* ep = g_ep + beg;
    int j = 0;
    for (; j + 4 <= len; j += 4) {
        const uint4 e4 = *(const uint4*)(ep + j);
        const uint4 ha = g_h[(size_t)(e4.x & 0xffffu) * 8 + q];
        const uint4 hb = g_h[(size_t)(e4.y & 0xffffu) * 8 + q];
        const uint4 hc = g_h[(size_t)(e4.z & 0xffffu) * 8 + q];
        const uint4 hd = g_h[(size_t)(e4.w & 0xffffu) * 8 + q];
        accum8(acc, edge_val(e4.x), ha);
        accum8(acc, edge_val(e4.y), hb);
        accum8(acc, edge_val(e4.z), hc);
        accum8(acc, edge_val(e4.w), hd);
    }
    for (; j < len; j++) {
        const unsigned e = ep[j];
        const uint4 h = g_h[(size_t)(e & 0xffffu) * 8 + q];
        accum8(acc, edge_val(e), h);
    }

    const float f = filt[(size_t)(b + 1) * NNODES + r];
    uint4 o;
    o.x = pack_h2(f * acc[0], f * acc[1]);
    o.y = pack_h2(f * acc[2], f * acc[3]);
    o.z = pack_h2(f * acc[4], f * acc[5]);
    o.w = pack_h2(f * acc[6], f * acc[7]);
    g_y[(size_t)row * 8 + q] = o;
}

// ---------------------------------------------------------------------------
// SpMM-2 (CSR gather, 4-edge batched): out[r] = bias + sum_b sum v_e * y[b][c]
// Restores g_hist = 0 after its final read (warp-local slot; warp-wide LDG
// precedes lane-0's STG in program order, no other warp reads the slot).
// ---------------------------------------------------------------------------
__global__ __launch_bounds__(256) void spmm2_csr(float* __restrict__ out,
                                                 const float* __restrict__ bias) {
    const int gid = blockIdx.x * 256 + threadIdx.x;
    const int r = gid >> 3;
    if (r >= NNODES) return;
    const int q = gid & 7;

    float acc[8];
    #pragma unroll
    for (int k = 0; k < 8; k++) acc[k] = bias[q * 8 + k];

    #pragma unroll
    for (int b = 0; b < ACT_B; b++) {
        const int row = b * NNODES + r;
        const int beg = g_start[row] + g_part[row >> 8];
        const int len = g_hist[row];
        if (q == 0) g_hist[row] = 0;
        const size_t ybase = (size_t)b * NNODES * 8;
        const unsigned* ep = g_ep + beg;
        int j = 0;
        for (; j + 4 <= len; j += 4) {
            const uint4 e4 = *(const uint4*)(ep + j);
            const uint4 ya = g_y[ybase + (size_t)(e4.x & 0xffffu) * 8 + q];
            const uint4 yb = g_y[ybase + (size_t)(e4.y & 0xffffu) * 8 + q];
            const uint4 yc = g_y[ybase + (size_t)(e4.z & 0xffffu) * 8 + q];
            const uint4 yd = g_y[ybase + (size_t)(e4.w & 0xffffu) * 8 + q];
            accum8(acc, edge_val(e4.x), ya);
            accum8(acc, edge_val(e4.y), yb);
            accum8(acc, edge_val(e4.z), yc);
            accum8(acc, edge_val(e4.w), yd);
        }
        for (; j < len; j++) {
            const unsigned e = ep[j];
            const uint4 yv = g_y[ybase + (size_t)(e & 0xffffu) * 8 + q];
            accum8(acc, edge_val(e), yv);
        }
    }
    float4* op = (float4*)(out + (size_t)r * F_OUT + q * 8);
    op[0] = make_float4(acc[0], acc[1], acc[2], acc[3]);
    op[1] = make_float4(acc[4], acc[5], acc[6], acc[7]);
}

// ---------------------------------------------------------------------------
// Launch: gemm(+hist), scan1, scan2, scatter, spmm1, spmm2(+hist restore)
// ---------------------------------------------------------------------------
extern "C" void kernel_launch(void* const* d_in, const int* in_sizes, int n_in,
                              void* d_out, int out_size) {
    const float* x    = (const float*)d_in[0];
    const float* wgt  = (const float*)d_in[1];
    const float* filt = (const float*)d_in[2];
    const float* bias = (const float*)d_in[3];
    const float* vals = (const float*)d_in[4];
    const int*   rows = (const int*)d_in[5];
    const int*   cols = (const int*)d_in[6];
    float* out = (float*)d_out;

    gemm_xw<<<NNODES / 16, 256>>>(x, wgt, rows);                   // #1
    scan1<<<NB1, 256>>>();                                         // #2
    scan2<<<1, 640>>>();                                           // #3
    scatter<<<(EDGES_T / 2 + 255) / 256, 256>>>(vals, rows, cols); // #4
    spmm1_csr<<<(ROWS_T * 8 + 255) / 256, 256>>>(filt);            // #5
    spmm2_csr<<<(NNODES * 8 + 255) / 256, 256>>>(out, bias);       // #6
}